// round 11
// baseline (speedup 1.0000x reference)
#include <cuda_runtime.h>
#include <cstdint>

// Problem constants (fixed shapes per reference setup_inputs)
#define BV 4
#define CV 1024
#define HV 64
#define WV 64
#define SV (HV*WV)          // 4096 spatial positions
#define AHV 7
#define AWV 7
#define NBINS (AHV*AWV)     // 49
#define CGRP 128            // channels per block (one permuted group)
#define NROI 2048
#define SPATIAL_SCALE 0.0625f

#define TR_BLOCKS (128 * 8 * 4)                 // 4096 transpose role blocks
#define PAR_BLOCKS ((NROI * NBINS + 255) / 256) // 392 param role blocks

// Scratch 1: features as [B, H, W, C'] where C' is permuted within each
// 128-channel group: the float4 at lane L holds channels {L, L+32, L+64, L+96}.
__device__ float g_feat_t[(size_t)BV * HV * WV * CV];

// Scratch 2: precomputed per-(roi,bin) params: { base_offset_bits, hr, wr, valid }
// base_offset excludes the channel-group offset (added per block).
__device__ float4 g_params[NROI * NBINS];   // 1.57 MB

// ---------------------------------------------------------------------------
// Pass 1 (fused): transpose+permute [B,C,H*W] -> [B,H*W,C_perm]  AND
// per-(roi,bin) param precompute, role selected by flat blockIdx.
// ---------------------------------------------------------------------------
__global__ __launch_bounds__(256)
void prep_kernel(const float* __restrict__ in, const float* __restrict__ rois) {
    const int bid = blockIdx.x;
    const int tid = threadIdx.x;

    if (bid < TR_BLOCKS) {
        // ---- transpose role: tile 128 channels x 32 spatial ----
        __shared__ float tile[CGRP][33];
        const int b   = bid >> 10;            // /1024
        const int c0g = (bid >> 7) & 7;       // /128 % 8
        const int s0  = (bid & 127) * 32;
        const int c0  = c0g * CGRP;
        const int tx  = tid & 31;
        const int ty  = tid >> 5;             // 0..7

        const float* src = in + (size_t)b * CV * SV;
        float* dst = g_feat_t + (size_t)b * SV * CV;

        #pragma unroll
        for (int cc = 0; cc < CGRP; cc += 8)
            tile[cc + ty][tx] = __ldcs(src + (size_t)(c0 + cc + ty) * SV + (s0 + tx));

        __syncthreads();

        #pragma unroll
        for (int s = ty; s < 32; s += 8) {
            float4 v;
            v.x = tile[tx      ][s];
            v.y = tile[tx + 32 ][s];
            v.z = tile[tx + 64 ][s];
            v.w = tile[tx + 96 ][s];
            *(float4*)(dst + (size_t)(s0 + s) * CV + c0 + 4 * tx) = v;
        }
    } else {
        // ---- param role ----
        const int idx = (bid - TR_BLOCKS) * 256 + tid;
        if (idx >= NROI * NBINS) return;
        const int n   = idx / NBINS;
        const int bin = idx % NBINS;

        const float* r = rois + (size_t)n * 5;
        const int   bi = (int)r[0];
        const float x1 = r[1] * SPATIAL_SCALE;
        const float y1 = r[2] * SPATIAL_SCALE;
        const float x2 = r[3] * SPATIAL_SCALE;
        const float y2 = r[4] * SPATIAL_SCALE;
        const float bin_w = fmaxf(x2 - x1, 0.0f) / (float)(AWV - 1);
        const float bin_h = fmaxf(y2 - y1, 0.0f) / (float)(AHV - 1);

        const int ph = bin / AWV;
        const int pw = bin % AWV;
        const float h  = y1 + (float)ph * bin_h;
        const float wq = x1 + (float)pw * bin_w;

        const float hstart = fminf(floorf(h),  (float)(HV - 2));
        const float wstart = fminf(floorf(wq), (float)(WV - 2));
        const float hr = h  - hstart;   // may exceed 1 near boundary (matches ref)
        const float wr = wq - wstart;

        const int hs = min(max((int)hstart, 0), HV - 2);
        const int ws = min(max((int)wstart, 0), WV - 2);
        const bool v = (h  >= 0.0f) && (h  < (float)HV) &&
                       (wq >= 0.0f) && (wq < (float)WV);

        const int base = ((bi * HV + hs) * WV + ws) * CV;
        g_params[idx] = make_float4(__int_as_float(base), hr, wr, v ? 1.0f : 0.0f);
    }
}

// ---------------------------------------------------------------------------
// Pass 2: RoIAlign gather + bilerp, distance-2 software pipeline.
// Block = 256 threads (8 warps) over 128 channels of one roi. Warp w handles
// bins j = w, w+8, ...; each lane gathers float4 (4 channels) per corner.
// TWO bins' corner loads are kept in flight per warp (32 KB/SM outstanding
// at 4 blocks/SM -> at the L1 saturation knee).
// ---------------------------------------------------------------------------
__global__ __launch_bounds__(256, 4)
void roialign_kernel(float* __restrict__ out) {
    __shared__ float4 sp[NBINS];                       // packed params
    __shared__ alignas(16) float stage[CGRP * NBINS];  // 25088 B == output slab

    const int n    = blockIdx.y;
    const int c0   = blockIdx.x * CGRP;
    const int tid  = threadIdx.x;
    const int w    = tid >> 5;               // warp 0..7
    const int lane = tid & 31;

    if (tid < NBINS)
        sp[tid] = __ldg(&g_params[n * NBINS + tid]);
    __syncthreads();

    const float* __restrict__ f = g_feat_t;
    const int lc = c0 + 4 * lane;

    // Prologue: slots 0 (j=w) and 1 (j=w+8), both always < 49.
    float4 p0 = sp[w];
    {
        const int o = __float_as_int(p0.x) + lc;
        // slot-0 corners
        // (declared below to keep liveness tight)
    }
    float4 ul0, ur0, dl0, dr0, ul1, ur1, dl1, dr1;
    {
        const int o0 = __float_as_int(p0.x) + lc;
        ul0 = *(const float4*)(f + o0);
        ur0 = *(const float4*)(f + o0 + CV);
        dl0 = *(const float4*)(f + o0 + WV * CV);
        dr0 = *(const float4*)(f + o0 + WV * CV + CV);
    }
    float4 p1 = sp[w + 8];
    {
        const int o1 = __float_as_int(p1.x) + lc;
        ul1 = *(const float4*)(f + o1);
        ur1 = *(const float4*)(f + o1 + CV);
        dl1 = *(const float4*)(f + o1 + WV * CV);
        dr1 = *(const float4*)(f + o1 + WV * CV + CV);
    }

    #pragma unroll
    for (int j = w; j < NBINS; j += 8) {
        // Prefetch bin j+16 into the slot being freed this iteration.
        float4 pn, uln, urn, dln, drn;
        const int jn = j + 16;
        if (jn < NBINS) {
            pn = sp[jn];
            const int on = __float_as_int(pn.x) + lc;
            uln = *(const float4*)(f + on);
            urn = *(const float4*)(f + on + CV);
            dln = *(const float4*)(f + on + WV * CV);
            drn = *(const float4*)(f + on + WV * CV + CV);
        }

        // Compute bin j from slot 0.
        const float hr = p0.y, wr = p0.z, vv = p0.w;
        float t, bo;
        t  = fmaf(wr, ur0.x - ul0.x, ul0.x);
        bo = fmaf(wr, dr0.x - dl0.x, dl0.x);
        stage[(lane      ) * NBINS + j] = fmaf(hr, bo - t, t) * vv;  // chan lane
        t  = fmaf(wr, ur0.y - ul0.y, ul0.y);
        bo = fmaf(wr, dr0.y - dl0.y, dl0.y);
        stage[(lane + 32 ) * NBINS + j] = fmaf(hr, bo - t, t) * vv;  // chan lane+32
        t  = fmaf(wr, ur0.z - ul0.z, ul0.z);
        bo = fmaf(wr, dr0.z - dl0.z, dl0.z);
        stage[(lane + 64 ) * NBINS + j] = fmaf(hr, bo - t, t) * vv;  // chan lane+64
        t  = fmaf(wr, ur0.w - ul0.w, ul0.w);
        bo = fmaf(wr, dr0.w - dl0.w, dl0.w);
        stage[(lane + 96 ) * NBINS + j] = fmaf(hr, bo - t, t) * vv;  // chan lane+96

        // Rotate: slot1 -> slot0, prefetched -> slot1.
        p0 = p1;  ul0 = ul1; ur0 = ur1; dl0 = dl1; dr0 = dr1;
        p1 = pn;  ul1 = uln; ur1 = urn; dl1 = dln; dr1 = drn;
    }
    __syncthreads();

    // Coalesced float4 writeback, evict-first (.cs) streaming stores.
    float4* __restrict__ o4 = (float4*)(out + ((size_t)n * CV + c0) * NBINS);
    const float4* __restrict__ s4 = (const float4*)stage;
    #pragma unroll
    for (int i = tid; i < (CGRP * NBINS) / 4; i += 256)
        __stcs(o4 + i, s4[i]);
}

// ---------------------------------------------------------------------------
extern "C" void kernel_launch(void* const* d_in, const int* in_sizes, int n_in,
                              void* d_out, int out_size) {
    const float* features = (const float*)d_in[0];
    const float* rois     = (const float*)d_in[1];
    float* out            = (float*)d_out;

    prep_kernel<<<TR_BLOCKS + PAR_BLOCKS, 256>>>(features, rois);

    dim3 grid(CV / CGRP, NROI);           // (8, 2048)
    roialign_kernel<<<grid, 256>>>(out);
}

// round 12
// speedup vs baseline: 1.0252x; 1.0252x over previous
#include <cuda_runtime.h>
#include <cstdint>

// Problem constants (fixed shapes per reference setup_inputs)
#define BV 4
#define CV 1024
#define HV 64
#define WV 64
#define SV (HV*WV)          // 4096 spatial positions
#define AHV 7
#define AWV 7
#define NBINS (AHV*AWV)     // 49
#define CGRP 128            // channels per block (one permuted group)
#define NROI 2048
#define SPATIAL_SCALE 0.0625f

#define TR_BLOCKS (128 * 8 * 4)                 // 4096 transpose role blocks
#define PAR_BLOCKS ((NROI * NBINS + 255) / 256) // 392 param role blocks

// Scratch 1: features as [B, H, W, C'] where C' is permuted within each
// 128-channel group: the float4 at lane L holds channels {L, L+32, L+64, L+96}.
__device__ float g_feat_t[(size_t)BV * HV * WV * CV];

// Scratch 2: precomputed per-(roi,bin) params: { base_offset_bits, hr, wr, valid }
// base_offset excludes the channel-group offset (added per block).
__device__ float4 g_params[NROI * NBINS];   // 1.57 MB

// ---------------------------------------------------------------------------
// Pass 1 (fused): transpose+permute [B,C,H*W] -> [B,H*W,C_perm]  AND
// per-(roi,bin) param precompute, role selected by flat blockIdx.
// ---------------------------------------------------------------------------
__global__ __launch_bounds__(256)
void prep_kernel(const float* __restrict__ in, const float* __restrict__ rois) {
    const int bid = blockIdx.x;
    const int tid = threadIdx.x;

    if (bid < TR_BLOCKS) {
        // ---- transpose role: tile 128 channels x 32 spatial ----
        __shared__ float tile[CGRP][33];
        const int b   = bid >> 10;            // /1024
        const int c0g = (bid >> 7) & 7;       // /128 % 8
        const int s0  = (bid & 127) * 32;
        const int c0  = c0g * CGRP;
        const int tx  = tid & 31;
        const int ty  = tid >> 5;             // 0..7

        const float* src = in + (size_t)b * CV * SV;
        float* dst = g_feat_t + (size_t)b * SV * CV;

        #pragma unroll
        for (int cc = 0; cc < CGRP; cc += 8)
            tile[cc + ty][tx] = __ldcs(src + (size_t)(c0 + cc + ty) * SV + (s0 + tx));

        __syncthreads();

        #pragma unroll
        for (int s = ty; s < 32; s += 8) {
            float4 v;
            v.x = tile[tx      ][s];
            v.y = tile[tx + 32 ][s];
            v.z = tile[tx + 64 ][s];
            v.w = tile[tx + 96 ][s];
            *(float4*)(dst + (size_t)(s0 + s) * CV + c0 + 4 * tx) = v;
        }
    } else {
        // ---- param role ----
        const int idx = (bid - TR_BLOCKS) * 256 + tid;
        if (idx >= NROI * NBINS) return;
        const int n   = idx / NBINS;
        const int bin = idx % NBINS;

        const float* r = rois + (size_t)n * 5;
        const int   bi = (int)r[0];
        const float x1 = r[1] * SPATIAL_SCALE;
        const float y1 = r[2] * SPATIAL_SCALE;
        const float x2 = r[3] * SPATIAL_SCALE;
        const float y2 = r[4] * SPATIAL_SCALE;
        const float bin_w = fmaxf(x2 - x1, 0.0f) / (float)(AWV - 1);
        const float bin_h = fmaxf(y2 - y1, 0.0f) / (float)(AHV - 1);

        const int ph = bin / AWV;
        const int pw = bin % AWV;
        const float h  = y1 + (float)ph * bin_h;
        const float wq = x1 + (float)pw * bin_w;

        const float hstart = fminf(floorf(h),  (float)(HV - 2));
        const float wstart = fminf(floorf(wq), (float)(WV - 2));
        const float hr = h  - hstart;   // may exceed 1 near boundary (matches ref)
        const float wr = wq - wstart;

        const int hs = min(max((int)hstart, 0), HV - 2);
        const int ws = min(max((int)wstart, 0), WV - 2);
        const bool v = (h  >= 0.0f) && (h  < (float)HV) &&
                       (wq >= 0.0f) && (wq < (float)WV);

        const int base = ((bi * HV + hs) * WV + ws) * CV;
        g_params[idx] = make_float4(__int_as_float(base), hr, wr, v ? 1.0f : 0.0f);
    }
}

// ---------------------------------------------------------------------------
// Gather + bilerp for one roi into the stage buffer (distance-1 pipeline,
// unconditional prefetch loads via index clamp).
// ---------------------------------------------------------------------------
__device__ __forceinline__
void do_roi(const float4* __restrict__ spr, const float* __restrict__ f,
            int lc, int w, int lane, float* __restrict__ stage) {
    // Prologue: bin j = w
    float4 p = spr[w];
    int off = __float_as_int(p.x) + lc;
    float4 ul = *(const float4*)(f + off);
    float4 ur = *(const float4*)(f + off + CV);
    float4 dl = *(const float4*)(f + off + WV * CV);
    float4 dr = *(const float4*)(f + off + WV * CV + CV);

    #pragma unroll
    for (int j = w; j < NBINS; j += 8) {
        // Unconditional prefetch of bin min(j+8, 48); clamp makes the last
        // iteration re-load bin 48 (discarded) instead of branching.
        const int jn = (j + 8 < NBINS) ? (j + 8) : (NBINS - 1);
        const float4 pn = spr[jn];
        const int on = __float_as_int(pn.x) + lc;
        const float4 uln = *(const float4*)(f + on);
        const float4 urn = *(const float4*)(f + on + CV);
        const float4 dln = *(const float4*)(f + on + WV * CV);
        const float4 drn = *(const float4*)(f + on + WV * CV + CV);

        const float hr = p.y, wr = p.z, vv = p.w;
        float t, bo;
        t  = fmaf(wr, ur.x - ul.x, ul.x);
        bo = fmaf(wr, dr.x - dl.x, dl.x);
        stage[(lane      ) * NBINS + j] = fmaf(hr, bo - t, t) * vv;  // chan lane
        t  = fmaf(wr, ur.y - ul.y, ul.y);
        bo = fmaf(wr, dr.y - dl.y, dl.y);
        stage[(lane + 32 ) * NBINS + j] = fmaf(hr, bo - t, t) * vv;  // chan lane+32
        t  = fmaf(wr, ur.z - ul.z, ul.z);
        bo = fmaf(wr, dr.z - dl.z, dl.z);
        stage[(lane + 64 ) * NBINS + j] = fmaf(hr, bo - t, t) * vv;  // chan lane+64
        t  = fmaf(wr, ur.w - ul.w, ul.w);
        bo = fmaf(wr, dr.w - dl.w, dl.w);
        stage[(lane + 96 ) * NBINS + j] = fmaf(hr, bo - t, t) * vv;  // chan lane+96

        p = pn; ul = uln; ur = urn; dl = dln; dr = drn;
    }
}

__device__ __forceinline__
void writeback(const float* __restrict__ stage, float* __restrict__ out,
               int n, int c0, int tid) {
    float4* __restrict__ o4 = (float4*)(out + ((size_t)n * CV + c0) * NBINS);
    const float4* __restrict__ s4 = (const float4*)stage;
    #pragma unroll
    for (int i = tid; i < (CGRP * NBINS) / 4; i += 256)
        __stcs(o4 + i, s4[i]);
}

// ---------------------------------------------------------------------------
// Pass 2: RoIAlign. Block = 256 threads (8 warps) over 128 channels of TWO
// rois processed back-to-back: one prologue (both rois' params), one tail,
// per two rois — amortizes block-edge overhead that capped L1 duty.
// ---------------------------------------------------------------------------
__global__ __launch_bounds__(256, 5)
void roialign_kernel(float* __restrict__ out) {
    __shared__ float4 sp[2][NBINS];                    // packed params, 2 rois
    __shared__ alignas(16) float stage[CGRP * NBINS];  // 25088 B == output slab

    const int n0   = blockIdx.y * 2;         // roi pair
    const int c0   = blockIdx.x * CGRP;
    const int tid  = threadIdx.x;
    const int w    = tid >> 5;               // warp 0..7
    const int lane = tid & 31;

    if (tid < 2 * NBINS) {
        const int which = tid / NBINS;
        const int bin   = tid - which * NBINS;
        sp[which][bin] = __ldg(&g_params[(n0 + which) * NBINS + bin]);
    }
    __syncthreads();

    const float* __restrict__ f = g_feat_t;
    const int lc = c0 + 4 * lane;

    // ---- roi A ----
    do_roi(sp[0], f, lc, w, lane, stage);
    __syncthreads();
    writeback(stage, out, n0, c0, tid);
    __syncthreads();           // stage free before roi B overwrites it

    // ---- roi B ----
    do_roi(sp[1], f, lc, w, lane, stage);
    __syncthreads();
    writeback(stage, out, n0 + 1, c0, tid);
}

// ---------------------------------------------------------------------------
extern "C" void kernel_launch(void* const* d_in, const int* in_sizes, int n_in,
                              void* d_out, int out_size) {
    const float* features = (const float*)d_in[0];
    const float* rois     = (const float*)d_in[1];
    float* out            = (float*)d_out;

    prep_kernel<<<TR_BLOCKS + PAR_BLOCKS, 256>>>(features, rois);

    dim3 grid(CV / CGRP, NROI / 2);       // (8, 1024)
    roialign_kernel<<<grid, 256>>>(out);
}